// round 6
// baseline (speedup 1.0000x reference)
#include <cuda_runtime.h>
#include <math_constants.h>

#define HH 512
#define NH 32
#define LL 8192
// l = 32*a + b, a in [0,256), b in [0,32)
// K[h,32a+b] = sum_n ( MR[a,n]*VR[n,b] + MI[a,n]*(-VI[n,b]) )
// M[a,n] = C2_n * w_n^(32a) ,  V[n,b] = w_n^b ,  C2 = 2*C*(w-1)/A

// Tables built by setup (device globals; no allocation allowed)
__device__ float2 g_V  [HH * NH * NH];   // [h][b][n] = (VR, -VI)   (b-major for coalesced store)
__device__ float2 g_TWr[HH * NH * NH];   // [h][r][n] = w^(32 r)
__device__ float2 g_Mq [HH * 8  * NH];   // [h][q][n] = C2 * w^(1024 q)

// ---------------- f32x2 packed helpers ----------------
static __device__ __forceinline__ unsigned long long pk2(float lo, float hi) {
    unsigned long long r;
    asm("mov.b64 %0, {%1, %2};" : "=l"(r) : "f"(lo), "f"(hi));
    return r;
}
static __device__ __forceinline__ void upk2(unsigned long long v, float& lo, float& hi) {
    asm("mov.b64 {%0, %1}, %2;" : "=f"(lo), "=f"(hi) : "l"(v));
}
static __device__ __forceinline__ unsigned long long fma2(unsigned long long a, unsigned long long b,
                                                          unsigned long long c) {
    unsigned long long d;
    asm("fma.rn.f32x2 %0, %1, %2, %3;" : "=l"(d) : "l"(a), "l"(b), "l"(c));
    return d;
}
static __device__ __forceinline__ float2 cmulf(float2 a, float2 b) {
    float2 r;
    r.x = fmaf(a.x, b.x, -(a.y * b.y));
    r.y = fmaf(a.x, b.y,  (a.y * b.x));
    return r;
}

// w^p for large p without fp64 transcendentals:
// phase = dtai*p ; reduce u = phase/pi mod 2 via double mults, then sincospif
static __device__ __forceinline__ float2 bigpow(float dtar, float dtai, float p) {
    double u = (double)dtai * (double)p * (1.0 / CUDART_PI);
    double f = u - 2.0 * rint(u * 0.5);          // in [-1, 1]
    float s, c;
    sincospif((float)f, &s, &c);
    float mag = expf(dtar * p);                  // underflow to 0 == true answer
    return make_float2(mag * c, mag * s);
}

// ---------------- Setup: one thread per (h,n) ----------------
__global__ void s4d_setup(const float* __restrict__ Cr, const float* __restrict__ Ci,
                          const float* __restrict__ ldt, const float* __restrict__ lar,
                          const float* __restrict__ Aim) {
    int idx = blockIdx.x * blockDim.x + threadIdx.x;
    if (idx >= HH * NH) return;
    int h = idx >> 5;
    int n = idx & 31;

    // fp32 discretization, matching reference rounding
    float dtf  = expf(ldt[h]);
    float arf  = -expf(lar[idx]);
    float aif  = Aim[idx];
    float dtar = arf * dtf;
    float dtai = aif * dtf;

    // base w = exp(dtA), fp32 (matches reference complex64 exp)
    float er, si, co;
    er = expf(dtar);
    sincosf(dtai, &si, &co);
    float2 w = make_float2(er * co, er * si);

    // C2 = 2 * C * (w - 1) / A, fp32 like the reference (2x folded in)
    float nr = w.x - 1.0f, ni = w.y;
    float den = arf * arf + aif * aif;
    float inv = 1.0f / den;
    float fr = (nr * arf + ni * aif) * inv;
    float fi = (ni * arf - nr * aif) * inv;
    float cr = Cr[idx], ci = Ci[idx];
    float2 C2 = make_float2(2.0f * (cr * fr - ci * fi),
                            2.0f * (cr * fi + ci * fr));

    // V[b] = w^b chain; stored b-major (coalesced across n), imag pre-negated
    {
        float2 v = make_float2(1.0f, 0.0f);
        float2* gv = g_V + h * (NH * NH) + n;
        #pragma unroll 4
        for (int b = 0; b < NH; ++b) {
            gv[b * NH] = make_float2(v.x, -v.y);
            v = cmulf(v, w);
        }
    }

    // W = w^32 (accurate anchor), TWr[r] = W^r chain
    float2 W = bigpow(dtar, dtai, 32.0f);
    {
        float2 x = make_float2(1.0f, 0.0f);
        float2* gt = g_TWr + h * (NH * NH) + n;
        #pragma unroll 4
        for (int r = 0; r < NH; ++r) {
            gt[r * NH] = x;
            x = cmulf(x, W);
        }
    }

    // Mq[q] = C2 * w^(1024 q), accurate bigpow anchors
    {
        float2* gm = g_Mq + h * (8 * NH) + n;
        #pragma unroll
        for (int q = 0; q < 8; ++q) {
            float2 J = bigpow(dtar, dtai, 1024.0f * (float)q);
            gm[q * NH] = cmulf(C2, J);
        }
    }
}

// ---------------- Main: block per h; register-tiled GEMM ----------------
// Thread tile: 8 a-rows (4 f32x2 pairs) x 8 b-cols -> 32 acc regs (f32x2)
// Thread grid: 32 a-groups x 4 b-groups = 128 threads; covers 256a x 32b = row h.
#define APAD 258                     // padded a-stride (even, breaks 16-way STS conflict)
__global__ void __launch_bounds__(128) s4d_main(float* __restrict__ out) {
    __shared__ __align__(16) float  sMR[16][APAD];
    __shared__ __align__(16) float  sMI[16][APAD];
    __shared__ __align__(16) float2 sV[NH][NH + 1];   // [n][b], padded

    int h   = blockIdx.x;
    int tid = threadIdx.x;
    int agroup = tid >> 2;           // 0..31
    int bgroup = tid & 3;            // 0..3
    int abase  = agroup * 8;
    int bbase  = bgroup * 8;

    // ---- load V (transpose b-major global -> [n][b] smem) ----
    {
        const float2* gv = g_V + h * (NH * NH);
        #pragma unroll
        for (int i = tid; i < NH * NH; i += 128) {
            int b = i >> 5, n = i & 31;
            sV[n][b] = gv[i];
        }
    }

    // ---- M-generation constants for this thread ----
    int nloc  = tid & 15;            // local n within chunk
    int ahalf = tid >> 4;            // 0..7 == q ; generates a = ahalf*32 + i

    unsigned long long acc[4][8];
    #pragma unroll
    for (int k = 0; k < 4; ++k)
        #pragma unroll
        for (int j = 0; j < 8; ++j) acc[k][j] = 0ULL;

    for (int chunk = 0; chunk < 2; ++chunk) {
        __syncthreads();             // previous GEMM done before overwriting sM
        // ---- build M chunk: n in [chunk*16, chunk*16+16), all 256 a ----
        {
            int n = chunk * 16 + nloc;
            float2 mq = g_Mq[h * (8 * NH) + ahalf * NH + n];
            const float2* twr = g_TWr + h * (NH * NH) + n;
            #pragma unroll 4
            for (int i = 0; i < 32; ++i) {
                float2 tw = twr[i * NH];
                float2 m  = cmulf(mq, tw);
                sMR[nloc][ahalf * 32 + i] = m.x;
                sMI[nloc][ahalf * 32 + i] = m.y;
            }
        }
        __syncthreads();

        // ---- GEMM over the 16 modes of this chunk ----
        #pragma unroll
        for (int nn = 0; nn < 16; ++nn) {
            int ng = chunk * 16 + nn;

            unsigned long long mr[4], mi[4];
            #pragma unroll
            for (int k = 0; k < 4; ++k) {
                float2 t = *(const float2*)&sMR[nn][abase + 2 * k];
                mr[k] = pk2(t.x, t.y);
                float2 u = *(const float2*)&sMI[nn][abase + 2 * k];
                mi[k] = pk2(u.x, u.y);
            }
            unsigned long long vr[8], vi[8];
            #pragma unroll
            for (int j = 0; j < 8; ++j) {
                float2 v = sV[ng][bbase + j];
                vr[j] = pk2(v.x, v.x);   //  VR dup
                vi[j] = pk2(v.y, v.y);   // -VI dup (pre-negated)
            }
            #pragma unroll
            for (int k = 0; k < 4; ++k)
                #pragma unroll
                for (int j = 0; j < 8; ++j) {
                    acc[k][j] = fma2(mr[k], vr[j], acc[k][j]);
                    acc[k][j] = fma2(mi[k], vi[j], acc[k][j]);
                }
        }
    }

    // ---- epilogue: acc[k][j] = (K[abase+2k, bbase+j], K[abase+2k+1, bbase+j]) ----
    float* op = out + h * LL;
    #pragma unroll
    for (int k = 0; k < 4; ++k) {
        float lo[8], hi[8];
        #pragma unroll
        for (int j = 0; j < 8; ++j) upk2(acc[k][j], lo[j], hi[j]);
        int a0 = abase + 2 * k;
        float4* p0 = (float4*)(op + a0 * NH + bbase);
        p0[0] = make_float4(lo[0], lo[1], lo[2], lo[3]);
        p0[1] = make_float4(lo[4], lo[5], lo[6], lo[7]);
        float4* p1 = (float4*)(op + (a0 + 1) * NH + bbase);
        p1[0] = make_float4(hi[0], hi[1], hi[2], hi[3]);
        p1[1] = make_float4(hi[4], hi[5], hi[6], hi[7]);
    }
}

extern "C" void kernel_launch(void* const* d_in, const int* in_sizes, int n_in,
                              void* d_out, int out_size) {
    const float* C_real     = (const float*)d_in[0];
    const float* C_imag     = (const float*)d_in[1];
    const float* log_dt     = (const float*)d_in[2];
    const float* log_a_real = (const float*)d_in[3];
    const float* A_imag     = (const float*)d_in[4];
    float* out = (float*)d_out;

    s4d_setup<<<(HH * NH + 255) / 256, 256>>>(C_real, C_imag, log_dt, log_a_real, A_imag);
    s4d_main<<<HH, 128>>>(out);
}

// round 7
// speedup vs baseline: 1.3071x; 1.3071x over previous
#include <cuda_runtime.h>
#include <math_constants.h>

#define HH   512
#define NH   32
#define LL   8192
#define CHUNKS 4            // per h-row: 4 chunks, each covers 2048 l-values
#define TSTEPS 64           // l-steps per lane (stride 32) per chunk
#define WIN  8              // steps per combine window

// Per-(h,n) constant table, 5 float2 slots: [h][slot][n]
//   0 : w^2048   1 : w^4096   2 : w^-32   3 : C2 = 2*C*(w-1)/A   4 : (T, -Q)
#define SLOTS 5
__device__ float2 g_tab[HH * SLOTS * NH];
// Lane-power table: g_pw4[h][j][lane] = (w_{2j}^lane, w_{2j+1}^lane)
__device__ float4 g_pw4[HH * 16 * NH];

// ---------------- f32x2 packed helpers ----------------
static __device__ __forceinline__ unsigned long long pk2(float lo, float hi) {
    unsigned long long r;
    asm("mov.b64 %0, {%1, %2};" : "=l"(r) : "f"(lo), "f"(hi));
    return r;
}
static __device__ __forceinline__ void upk2(unsigned long long v, float& lo, float& hi) {
    asm("mov.b64 {%0, %1}, %2;" : "=f"(lo), "=f"(hi) : "l"(v));
}
static __device__ __forceinline__ unsigned long long mul2(unsigned long long a, unsigned long long b) {
    unsigned long long d;
    asm("mul.rn.f32x2 %0, %1, %2;" : "=l"(d) : "l"(a), "l"(b));
    return d;
}
static __device__ __forceinline__ unsigned long long add2(unsigned long long a, unsigned long long b) {
    unsigned long long d;
    asm("add.rn.f32x2 %0, %1, %2;" : "=l"(d) : "l"(a), "l"(b));
    return d;
}
static __device__ __forceinline__ unsigned long long fma2(unsigned long long a, unsigned long long b,
                                                          unsigned long long c) {
    unsigned long long d;
    asm("fma.rn.f32x2 %0, %1, %2, %3;" : "=l"(d) : "l"(a), "l"(b), "l"(c));
    return d;
}
static __device__ __forceinline__ float2 cmulf(float2 a, float2 b) {
    float2 r;
    r.x = fmaf(a.x, b.x, -(a.y * b.y));
    r.y = fmaf(a.x, b.y,  (a.y * b.x));
    return r;
}

// w^p for large p without fp64 transcendentals
static __device__ __forceinline__ float2 bigpow(float dtar, float dtai, float p) {
    double u = (double)dtai * (double)p * (1.0 / CUDART_PI);
    double f = u - 2.0 * rint(u * 0.5);          // in [-1, 1]
    float s, c;
    sincospif((float)f, &s, &c);
    float mag = expf(dtar * p);                  // underflow to 0 == true answer
    return make_float2(mag * c, mag * s);
}

// ---------------- Fused setup: constants + lane-power table ----------------
__global__ void __launch_bounds__(512) s4d_setup(const float* __restrict__ Cr,
                                                 const float* __restrict__ Ci,
                                                 const float* __restrict__ ldt,
                                                 const float* __restrict__ lar,
                                                 const float* __restrict__ Aim) {
    __shared__ float2 lev[5][NH];     // w^(2^k), k=0..4

    int h = blockIdx.x;
    int t = threadIdx.x;

    if (t < NH) {
        int n = t;
        int idx = h * NH + n;

        float dtf  = expf(ldt[h]);
        float arf  = -expf(lar[idx]);
        float aif  = Aim[idx];
        float dtar = arf * dtf;
        float dtai = aif * dtf;

        float er, si, co;
        er = expf(dtar);
        sincosf(dtai, &si, &co);
        float2 w = make_float2(er * co, er * si);

        float nr = w.x - 1.0f, ni = w.y;
        float den = arf * arf + aif * aif;
        float inv = 1.0f / den;
        float fr = (nr * arf + ni * aif) * inv;
        float fi = (ni * arf - nr * aif) * inv;
        float cr = Cr[idx], ci = Ci[idx];
        float2 C2 = make_float2(2.0f * (cr * fr - ci * fi),
                                2.0f * (cr * fi + ci * fr));

        float2 x = w;
        #pragma unroll
        for (int k = 0; k < 5; ++k) {
            lev[k][n] = x;
            float tr = fmaf(x.x, x.x, -(x.y * x.y));
            x.y = 2.0f * x.x * x.y;
            x.x = tr;
        }
        float2 w32 = x;

        float2* dst = g_tab + (h * SLOTS) * NH + n;
        dst[0 * NH] = bigpow(dtar, dtai, 2048.0f);
        dst[1 * NH] = bigpow(dtar, dtai, 4096.0f);
        float q  = fmaf(w32.x, w32.x, w32.y * w32.y);
        float qi = 1.0f / q;
        dst[2 * NH] = make_float2(w32.x * qi, -w32.y * qi);   // w^-32
        dst[3 * NH] = C2;
        dst[4 * NH] = make_float2(2.0f * w32.x, -q);          // (T, -Q)
    }
    __syncthreads();

    int l = t >> 4;          // 0..31
    int j = t & 15;          // mode pair
    int m0 = 2 * j, m1 = 2 * j + 1;
    float2 a = make_float2(1.0f, 0.0f);
    float2 b = make_float2(1.0f, 0.0f);
    #pragma unroll
    for (int k = 0; k < 5; ++k) {
        if ((l >> k) & 1) {
            a = cmulf(a, lev[k][m0]);
            b = cmulf(b, lev[k][m1]);
        }
    }
    g_pw4[(h * 16 + j) * NH + l] = make_float4(a.x, a.y, b.x, b.y);
}

// ---------------- Main ----------------
// Block = 128 threads (4 warps). Block handles (h, cpair): chunks cpair*2 + {0,1}.
// Warp w: chunk p = w>>1 (local), mode-half halfm = w&1 (modes halfm*16..+16).
// Per step each warp emits a 32-lane partial into sBuf; every WIN steps all 128
// threads combine the two halves and store coalesced float4 to gmem.
__global__ void __launch_bounds__(128, 4) s4d_main(float* __restrict__ out) {
    __shared__ float2 sC[2][NH];        // C2 * J(chunk)        (per local chunk)
    __shared__ float2 sD[2][NH];        // C2 * J * w^-32
    __shared__ float2 sT[NH];           // (T, -Q)  (chunk-independent)
    __shared__ float  sBuf[4][WIN * 32];

    int h     = blockIdx.x >> 1;
    int cpair = blockIdx.x & 1;
    int tid   = threadIdx.x;
    int wid   = tid >> 5;
    int lane  = tid & 31;
    int p     = wid >> 1;               // local chunk 0/1
    int halfm = wid & 1;                // mode half
    int c     = cpair * 2 + p;          // global chunk 0..3

    // Phase 1: half-0 warps build per-chunk constants; warp 0 builds sT.
    if (halfm == 0) {
        const float2* gt = g_tab + (h * SLOTS) * NH + lane;
        float2 w2k  = gt[0 * NH];
        float2 w4k  = gt[1 * NH];
        float2 wm32 = gt[2 * NH];
        float2 C2   = gt[3 * NH];
        float2 J = make_float2(1.0f, 0.0f);
        if (c & 1) J = w2k;
        if (c & 2) J = cmulf(J, w4k);
        float2 C2J = cmulf(C2, J);
        sC[p][lane] = C2J;
        sD[p][lane] = cmulf(C2J, wm32);
        if (wid == 0) sT[lane] = gt[4 * NH];
    }
    __syncthreads();

    // Phase 2: per-thread init, 8 mode-pairs
    unsigned long long cur[8], prv[8], T2[8], Qn[8];
    {
        const float4* pw = g_pw4 + (h * 16 + halfm * 8) * NH + lane;
        #pragma unroll
        for (int j = 0; j < 8; ++j) {
            int jj = halfm * 8 + j;
            int m0 = 2 * jj, m1 = 2 * jj + 1;
            float4 v = pw[j * NH];                   // coalesced across lanes
            float2 wl0 = make_float2(v.x, v.y);
            float2 wl1 = make_float2(v.z, v.w);
            float2 pa = cmulf(wl0, sC[p][m0]);
            float2 pb = cmulf(wl1, sC[p][m1]);
            float2 qa = cmulf(wl0, sD[p][m0]);
            float2 qb = cmulf(wl1, sD[p][m1]);
            cur[j] = pk2(pa.x, pb.x);
            prv[j] = pk2(qa.x, qb.x);
            T2[j]  = pk2(sT[m0].x, sT[m1].x);        //  T  = 2 Re(w^32)
            Qn[j]  = pk2(sT[m0].y, sT[m1].y);        // -Q  = -|w^32|^2
        }
    }

    float* opc = out + h * LL + cpair * 2 * (LL / CHUNKS);  // base for this block

    #pragma unroll 1
    for (int win = 0; win < TSTEPS / WIN; ++win) {
        // ---- WIN steps, partials to smem ----
        #pragma unroll
        for (int s = 0; s < WIN; s += 2) {
            // emit sum(cur) at step s
            {
                unsigned long long s4[4];
                #pragma unroll
                for (int j = 0; j < 4; ++j) s4[j] = add2(cur[2 * j], cur[2 * j + 1]);
                unsigned long long acc = add2(add2(s4[0], s4[1]), add2(s4[2], s4[3]));
                float lo, hi;
                upk2(acc, lo, hi);
                sBuf[wid][s * 32 + lane] = lo + hi;
            }
            #pragma unroll
            for (int j = 0; j < 8; ++j)
                prv[j] = fma2(T2[j], cur[j], mul2(Qn[j], prv[j]));

            // emit sum(prv) at step s+1
            {
                unsigned long long s4[4];
                #pragma unroll
                for (int j = 0; j < 4; ++j) s4[j] = add2(prv[2 * j], prv[2 * j + 1]);
                unsigned long long acc = add2(add2(s4[0], s4[1]), add2(s4[2], s4[3]));
                float lo, hi;
                upk2(acc, lo, hi);
                sBuf[wid][(s + 1) * 32 + lane] = lo + hi;
            }
            #pragma unroll
            for (int j = 0; j < 8; ++j)
                cur[j] = fma2(T2[j], prv[j], mul2(Qn[j], cur[j]));
        }
        __syncthreads();

        // ---- combine halves + coalesced store ----
        {
            int p2 = tid >> 6;          // local chunk handled by this 64-thread group
            int i  = tid & 63;          // float4 index within the 256-float window
            const float4* b0 = (const float4*)sBuf[2 * p2];
            const float4* b1 = (const float4*)sBuf[2 * p2 + 1];
            float4 x = b0[i];
            float4 y = b1[i];
            float4 r = make_float4(x.x + y.x, x.y + y.y, x.z + y.z, x.w + y.w);
            float* dst = opc + p2 * (LL / CHUNKS) + win * (WIN * 32) + i * 4;
            __stcs((float4*)dst, r);
        }
        __syncthreads();
    }
}

extern "C" void kernel_launch(void* const* d_in, const int* in_sizes, int n_in,
                              void* d_out, int out_size) {
    const float* C_real     = (const float*)d_in[0];
    const float* C_imag     = (const float*)d_in[1];
    const float* log_dt     = (const float*)d_in[2];
    const float* log_a_real = (const float*)d_in[3];
    const float* A_imag     = (const float*)d_in[4];
    float* out = (float*)d_out;

    s4d_setup<<<HH, 512>>>(C_real, C_imag, log_dt, log_a_real, A_imag);
    s4d_main<<<HH * 2, 128>>>(out);
}